// round 2
// baseline (speedup 1.0000x reference)
#include <cuda_runtime.h>
#include <math.h>

#define NN    8192
#define EE    262144
#define CC    64
#define ELLW  128          // Poisson(32) tail beyond 128 ~ 1e-40
#define TBITS 22
#define TSZ   (1 << TBITS) // 4M slots
#define TMASK (TSZ - 1)

// ---- scratch (__device__ globals; zero-initialized at module load) ----
__device__ unsigned long long g_hash[TSZ];   // 32 MB; all-zero between calls
__device__ int   g_slotidx[EE];              // per-edge resolved hash slot
__device__ float g_deg[NN];
__device__ int   g_cnt[NN];
__device__ int   g_ellc[NN * ELLW];
__device__ float g_ellw[NN * ELLW];
__device__ float g_T1[NN * CC];
__device__ float g_T2[NN * CC];
__device__ float g_gate;
__device__ int   g_is32;                     // edge_index dtype flag

__device__ __forceinline__ unsigned hash_key(unsigned key) {
    return (key * 2654435761u) >> (32 - TBITS);
}

__device__ __forceinline__ void load_rc(const void* ei, int j, int& r, int& c) {
    if (g_is32) {
        const int* e = (const int*)ei;
        r = e[j]; c = e[EE + j];
    } else {
        const long long* e = (const long long*)ei;
        r = (int)e[j]; c = (int)e[EE + j];
    }
}

// 0) detect edge_index dtype (int32 vs int64)
__global__ void k_detect(const void* ei) {
    const long long* e64 = (const long long*)ei;
    int bad = 0;
    for (int i = 0; i < 64; i++) {
        long long v = e64[i];
        if (v < 0 || v >= NN) bad = 1;
    }
    g_is32 = bad;
}

// 1) reset per-row state, compute sigmoid gate
__global__ void k_init(const float* __restrict__ aw) {
    int i = blockIdx.x * blockDim.x + threadIdx.x;
    if (i < NN) { g_deg[i] = 1.0f; g_cnt[i] = 0; }
    if (i == 0) g_gate = 1.0f / (1.0f + expf(-aw[0]));
}

// 2) hash-insert with last-write-wins (max edge id) per (r,c) key
__global__ void k_insert(const void* __restrict__ ei) {
    int j = blockIdx.x * blockDim.x + threadIdx.x;
    if (j >= EE) return;
    int r, c; load_rc(ei, j, r, c);
    unsigned key = ((unsigned)r << 13) | (unsigned)c;        // 26 bits
    unsigned long long entry =
        ((unsigned long long)(key + 1) << 20) | (unsigned)(j + 1);
    unsigned h = hash_key(key);
    for (;;) {
        unsigned long long cur = g_hash[h];
        if (cur == 0ULL) {
            unsigned long long old = atomicCAS(&g_hash[h], 0ULL, entry);
            if (old == 0ULL) break;
            cur = old;
        }
        if ((cur >> 20) == (unsigned long long)(key + 1)) {
            atomicMax(&g_hash[h], entry);
            break;
        }
        h = (h + 1) & TMASK;
    }
}

// 3) winners -> ELL lists + degree accumulation; record slot for clearing
__global__ void k_winner(const void* __restrict__ ei,
                         const float* __restrict__ ew) {
    int j = blockIdx.x * blockDim.x + threadIdx.x;
    if (j >= EE) return;
    int r, c; load_rc(ei, j, r, c);
    unsigned key = ((unsigned)r << 13) | (unsigned)c;
    unsigned h = hash_key(key);
    for (;;) {
        unsigned long long cur = g_hash[h];
        if ((cur >> 20) == (unsigned long long)(key + 1)) {
            g_slotidx[j] = (int)h;
            if ((cur & 0xFFFFFULL) == (unsigned long long)(j + 1)) {
                float awv = ew[j] * g_gate;
                int pos = atomicAdd(&g_cnt[r], 1);
                if (pos < ELLW) {
                    g_ellc[r * ELLW + pos] = c;
                    g_ellw[r * ELLW + pos] = awv;
                }
                atomicAdd(&g_deg[r], awv);
            }
            break;
        }
        h = (h + 1) & TMASK;
    }
}

// 4) restore hash table to all-zero (graph-replay invariant)
__global__ void k_clear(const void* __restrict__ ei) {
    int j = blockIdx.x * blockDim.x + threadIdx.x;
    if (j >= EE) return;
    g_hash[g_slotidx[j]] = 0ULL;
}

// 5/6) SpMM: mode 1: T1 = L x ; mode 2: T2 = 2 L T1 - x
// one warp per row; each lane owns 2 channels (float2)
__global__ void k_spmm(const float* __restrict__ x, int mode) {
    int gtid = blockIdx.x * blockDim.x + threadIdx.x;
    int r = gtid >> 5;
    int lane = gtid & 31;
    if (r >= NN) return;

    const float2* z2 = (mode == 1) ? (const float2*)x : (const float2*)g_T1;
    float dr = g_deg[r];
    float sr = rsqrtf(dr);
    float diag = 1.0f - 1.0f / dr;

    float2 acc = z2[r * 32 + lane];
    acc.x *= diag; acc.y *= diag;

    int nnz = min(g_cnt[r], ELLW);
    int base = r * ELLW;
    for (int k = 0; k < nnz; k++) {
        int   c = g_ellc[base + k];
        float w = g_ellw[base + k];
        float coef = -sr * w * rsqrtf(g_deg[c]);
        float2 zc = z2[c * 32 + lane];
        acc.x += coef * zc.x;
        acc.y += coef * zc.y;
    }

    if (mode == 1) {
        ((float2*)g_T1)[r * 32 + lane] = acc;
    } else {
        float2 x0 = ((const float2*)x)[r * 32 + lane];
        acc.x = 2.0f * acc.x - x0.x;
        acc.y = 2.0f * acc.y - x0.y;
        ((float2*)g_T2)[r * 32 + lane] = acc;
    }
}

// 7) fused output GEMM: out = x@W0 + T1@W1 + T2@W2 + bias
__global__ void k_out(const float* __restrict__ x,
                      const float* __restrict__ w,
                      const float* __restrict__ bias,
                      float* __restrict__ out) {
    __shared__ float ws[3 * 64 * 64];  // 48 KB
    int tid = threadIdx.x;
    for (int i = tid; i < 3 * 64 * 64; i += 256) ws[i] = w[i];
    __syncthreads();

    int o  = tid & 63;
    int ty = tid >> 6;        // 0..3
    int r0 = blockIdx.x * 64;
    float b = __ldg(&bias[o]);

    for (int rr = 0; rr < 16; rr++) {
        int r = r0 + rr * 4 + ty;
        const float* x0 = x    + r * 64;
        const float* t1 = g_T1 + r * 64;
        const float* t2 = g_T2 + r * 64;
        float acc = b;
        #pragma unroll 16
        for (int i = 0; i < 64; i++) {
            acc += x0[i] * ws[i * 64 + o]
                 + t1[i] * ws[4096 + i * 64 + o]
                 + t2[i] * ws[8192 + i * 64 + o];
        }
        out[r * 64 + o] = acc;
    }
}

extern "C" void kernel_launch(void* const* d_in, const int* in_sizes, int n_in,
                              void* d_out, int out_size) {
    const float* x    = (const float*)d_in[0];
    const void*  ei   = (const void*)d_in[1];
    const float* ew   = (const float*)d_in[2];
    const float* w    = (const float*)d_in[3];
    const float* aw   = (const float*)d_in[4];
    const float* bias = (const float*)d_in[5];
    float* out = (float*)d_out;

    k_detect<<<1, 1>>>(ei);
    k_init  <<<32, 256>>>(aw);
    k_insert<<<EE / 256, 256>>>(ei);
    k_winner<<<EE / 256, 256>>>(ei, ew);
    k_clear <<<EE / 256, 256>>>(ei);
    k_spmm  <<<NN * 32 / 256, 256>>>(x, 1);   // T1 = L x
    k_spmm  <<<NN * 32 / 256, 256>>>(x, 2);   // T2 = 2 L T1 - x
    k_out   <<<NN / 64, 256>>>(x, w, bias, out);
}